// round 15
// baseline (speedup 1.0000x reference)
#include <cuda_runtime.h>
#include <cuda_fp16.h>
#include <math.h>

#define NBT 32
#define CCH 192
#define TOT (NBT*CCH*1024)
typedef unsigned int uint32;

// fp32 scratch
__device__ float g_xs [TOT];          // z (bhw,c,t) in pass2
__device__ float g_y  [TOT];
__device__ float g_yt [TOT];
__device__ float g_stat[NBT*32*2];
// fp16 scratch
__device__ __half g_nrm16[32768*192];
__device__ __half g_qk16 [32768*384];
__device__ __half g_v16T [32768*192];
__device__ __half g_att16[32768*192];
__device__ __half g_w16  [294912];

// ---- helpers ----------------------------------------------------------------
__device__ __forceinline__ void mmah(float4 &c, const uint32* a, uint32 b0, uint32 b1) {
    asm("mma.sync.aligned.m16n8k16.row.col.f32.f16.f16.f32 "
        "{%0,%1,%2,%3},{%4,%5,%6,%7},{%8,%9},{%0,%1,%2,%3};"
        : "+f"(c.x), "+f"(c.y), "+f"(c.z), "+f"(c.w)
        : "r"(a[0]), "r"(a[1]), "r"(a[2]), "r"(a[3]), "r"(b0), "r"(b1));
}
__device__ __forceinline__ uint32 sptr(const void* p) {
    return (uint32)__cvta_generic_to_shared(p);
}
__device__ __forceinline__ void ldsm4(uint32* r, uint32 addr) {
    asm volatile("ldmatrix.sync.aligned.m8n8.x4.shared.b16 {%0,%1,%2,%3}, [%4];"
        : "=r"(r[0]), "=r"(r[1]), "=r"(r[2]), "=r"(r[3]) : "r"(addr));
}
__device__ __forceinline__ void cp16(uint32 s, const void* g) {
    asm volatile("cp.async.ca.shared.global [%0], [%1], 16;" :: "r"(s), "l"(g));
}
__device__ __forceinline__ void cp_commit() { asm volatile("cp.async.commit_group;"); }
template<int N> __device__ __forceinline__ void cp_wait() {
    asm volatile("cp.async.wait_group %0;" :: "n"(N));
}

// ---------------------------------------------------------------------------
// Weight fp16 prep
// ---------------------------------------------------------------------------
__global__ void k_wprep(const float* __restrict__ qw, const float* __restrict__ pw,
                        const float* __restrict__ qtw, const float* __restrict__ ptw) {
    int i = blockIdx.x * 1024 + threadIdx.x;
    float v;
    if      (i < 110592) v = qw[i];
    else if (i < 147456) v = pw[i - 110592];
    else if (i < 258048) v = qtw[i - 147456];
    else                 v = ptw[i - 258048];
    g_w16[i] = __float2half(v);
}

// ---------------------------------------------------------------------------
// GroupNorm pass 1 stats
// ---------------------------------------------------------------------------
__global__ void k_gn1s(const float* __restrict__ x) {
    int n = blockIdx.x >> 5, g = blockIdx.x & 31;
    int b = n >> 4, t = n & 15;
    const float* xb = x + (((size_t)(b * CCH + g * 6) * 16 + t) << 10);
    int tid = threadIdx.x;
    float s = 0.f, q = 0.f;
    for (int i = tid; i < 6144; i += 256) {
        float v = xb[((size_t)(i >> 10) << 14) + (i & 1023)];
        s += v; q += v * v;
    }
    __shared__ float rs[256], rq[256];
    rs[tid] = s; rq[tid] = q;
    __syncthreads();
    for (int st = 128; st > 0; st >>= 1) {
        if (tid < st) { rs[tid] += rs[tid + st]; rq[tid] += rq[tid + st]; }
        __syncthreads();
    }
    if (tid == 0) {
        float mean = rs[0] / 6144.f;
        float var  = rq[0] / 6144.f - mean * mean;
        g_stat[blockIdx.x * 2]     = mean;
        g_stat[blockIdx.x * 2 + 1] = rsqrtf(var + 1e-5f);
    }
}

// ---------------------------------------------------------------------------
// GroupNorm pass 1 apply, tiled coalesced
// ---------------------------------------------------------------------------
__global__ __launch_bounds__(256) void k_gn1at(const float* __restrict__ x,
                                               const float* __restrict__ gam,
                                               const float* __restrict__ bet) {
    __shared__ __half sbuf[64 * 200];
    const int hw0 = blockIdx.x * 64, bt = blockIdx.y;
    const int b = bt >> 4, t = bt & 15;
    const int tid = threadIdx.x;
    #pragma unroll
    for (int rep = 0; rep < 3; rep++) {
        const int c = rep * 64 + (tid >> 2);
        const int hwq = (tid & 3) * 16;
        const int g = c / 6;
        const float mu = g_stat[(bt * 32 + g) * 2];
        const float iv = g_stat[(bt * 32 + g) * 2 + 1];
        const float ga = gam[c] * iv;
        const float be = bet[c] - mu * ga;
        const float* src = x + (((size_t)(b * CCH + c) * 16 + t) << 10) + hw0 + hwq;
        #pragma unroll
        for (int j = 0; j < 16; j += 4) {
            float4 v = *(const float4*)(src + j);
            sbuf[(hwq + j + 0) * 200 + c] = __float2half(v.x * ga + be);
            sbuf[(hwq + j + 1) * 200 + c] = __float2half(v.y * ga + be);
            sbuf[(hwq + j + 2) * 200 + c] = __float2half(v.z * ga + be);
            sbuf[(hwq + j + 3) * 200 + c] = __float2half(v.w * ga + be);
        }
    }
    __syncthreads();
    #pragma unroll
    for (int i = tid; i < 1536; i += 256) {
        int tok = i / 24, seg = i - tok * 24;
        *(uint4*)(g_nrm16 + ((size_t)(bt * 1024 + hw0 + tok)) * 192 + seg * 8) =
            *(const uint4*)(sbuf + tok * 200 + seg * 8);
    }
}

// ---------------------------------------------------------------------------
// GroupNorm pass 2
// ---------------------------------------------------------------------------
__global__ void k_gn2h(const float* __restrict__ X, const float* __restrict__ gam,
                       const float* __restrict__ bet, __half* __restrict__ out16) {
    int n = blockIdx.x;
    __shared__ float buf[3072];
    __shared__ float mu[32], iv[32];
    int tid = threadIdx.x;
    const float4* xb = (const float4*)(X + (size_t)n * 3072);
    for (int i = tid; i < 768; i += 128) ((float4*)buf)[i] = xb[i];
    __syncthreads();
    int w = tid >> 5, lane = tid & 31;
    for (int g = w; g < 32; g += 4) {
        float v0 = buf[g * 96 + lane], v1 = buf[g * 96 + 32 + lane], v2 = buf[g * 96 + 64 + lane];
        float s = v0 + v1 + v2, q = v0 * v0 + v1 * v1 + v2 * v2;
        #pragma unroll
        for (int off = 16; off; off >>= 1) {
            s += __shfl_xor_sync(0xffffffffu, s, off);
            q += __shfl_xor_sync(0xffffffffu, q, off);
        }
        if (lane == 0) {
            float m = s / 96.f, va = q / 96.f - m * m;
            mu[g] = m; iv[g] = rsqrtf(va + 1e-5f);
        }
    }
    __syncthreads();
    __half* ob = out16 + (size_t)n * 3072;
    for (int j = tid; j < 3072; j += 128) {
        int t = j / 192, c = j - t * 192;
        int g = c / 6;
        ob[j] = __float2half((buf[c * 16 + t] - mu[g]) * iv[g] * gam[c] + bet[c]);
    }
}

// ---------------------------------------------------------------------------
// c-blocked transposes
// ---------------------------------------------------------------------------
__global__ __launch_bounds__(256) void k_transpose2c() {  // y (bt,c,hw) -> yt (bhw,c,t)
    __shared__ float sb[5168];
    const int hw0 = blockIdx.x * 64, c0 = blockIdx.y * 4, b = blockIdx.z;
    const int tid = threadIdx.x, w = tid >> 5, lane = tid & 31;
    #pragma unroll
    for (int it = 0; it < 8; it++) {
        int p = it * 8 + w;
        int c = p >> 4, t = p & 15;
        float2 v = *(const float2*)&g_y[(((size_t)(b * 16 + t) * CCH + c0 + c) << 10)
                                        + hw0 + lane * 2];
        sb[c * 1296 + (lane * 2) * 20 + t]     = v.x;
        sb[c * 1296 + (lane * 2 + 1) * 20 + t] = v.y;
    }
    __syncthreads();
    #pragma unroll
    for (int i2 = 0; i2 < 4; i2++) {
        int u = tid + 256 * i2;
        int hw = u >> 4, q = u & 15;
        int c = q >> 2, t4 = (q & 3) * 4;
        *(float4*)&g_yt[((size_t)(b * 1024 + hw0 + hw) * CCH + c0 + c) * 16 + t4] =
            *(const float4*)&sb[c * 1296 + hw * 20 + t4];
    }
}

__global__ __launch_bounds__(256) void k_transpose3c(float* __restrict__ out) {
    __shared__ float sb[5168];
    const int hw0 = blockIdx.x * 64, c0 = blockIdx.y * 4, b = blockIdx.z;
    const int tid = threadIdx.x, w = tid >> 5, lane = tid & 31;
    #pragma unroll
    for (int i2 = 0; i2 < 4; i2++) {
        int u = tid + 256 * i2;
        int hw = u >> 4, q = u & 15;
        int c = q >> 2, t4 = (q & 3) * 4;
        *(float4*)&sb[c * 1296 + hw * 20 + t4] =
            *(const float4*)&g_xs[((size_t)(b * 1024 + hw0 + hw) * CCH + c0 + c) * 16 + t4];
    }
    __syncthreads();
    #pragma unroll
    for (int it = 0; it < 8; it++) {
        int p = it * 8 + w;
        int c = p >> 4, t = p & 15;
        float2 v = make_float2(sb[c * 1296 + (lane * 2) * 20 + t],
                               sb[c * 1296 + (lane * 2 + 1) * 20 + t]);
        *(float2*)&out[(((size_t)(b * CCH + c0 + c) * 16 + t) << 10) + hw0 + lane * 2] = v;
    }
}

// ---------------------------------------------------------------------------
// QKV conv, X-persistent, 256 threads / 8 warps (warp tile 16o x 64tok).
// Grid (tokenTiles, 3 heads). smem halves: X [0,25600) t*200+k;
// W [25600,30720) buf*2560+o*40+k; E [30720,39936). 79,872 B.
// ---------------------------------------------------------------------------
#define CONVQ_SMEM 79872

__global__ __launch_bounds__(256, 2) void k_convq(
    const __half* __restrict__ X, const __half* __restrict__ W,
    const float* __restrict__ bias,
    __half* __restrict__ outqk, __half* __restrict__ outv, int ls) {
    extern __shared__ __half SM[];
    const int tid = threadIdx.x, lane = tid & 31, w = tid >> 5;
    const int r = lane >> 2, tg = lane & 3;
    const int g0 = blockIdx.x * 128, ha = blockIdx.y;
    const int L = 1 << ls, Lm1 = L - 1;
    const int aRow = (lane & 7) + 8 * ((lane >> 3) & 1);
    const int aCol = 8 * (lane >> 4);
    const int bRow = (lane & 7) + 8 * (lane >> 4);
    const int bCol = 8 * ((lane >> 3) & 1);
    const int ob0 = (w >> 1) * 16, coff = (w & 1) * 64;
    const int wo = tid & 63, wk8 = (tid >> 6) * 8;
    const __half* wbase = W + (size_t)(ha * 192) * 192;
    __half* E = SM + 30720;

    // stage entire X tile (group 0)
    {
        const int stok = tid >> 1, xh = (tid & 1) * 96;
        const __half* xsrc = X + (size_t)(g0 + stok) * 192 + xh;
        #pragma unroll
        for (int s = 0; s < 12; s++)
            cp16(sptr(&SM[stok * 200 + xh + s * 8]), xsrc + s * 8);
        cp_commit();
    }
    // W chunk 0
    cp16(sptr(&SM[25600 + wo * 40 + wk8]), wbase + (size_t)wo * 192 + wk8);
    cp_commit();

    for (int i = 0; i < 3; i++) {
        float4 acc[8];
        #pragma unroll
        for (int nt = 0; nt < 8; nt++) acc[nt] = make_float4(0.f, 0.f, 0.f, 0.f);

        for (int c = 0; c < 6; c++) {
            const int m = i * 6 + c;
            const int buf = m & 1;
            if (m < 17) {
                const int mn = m + 1;
                const int mi = mn / 6, mc = mn - mi * 6;
                cp16(sptr(&SM[25600 + (buf ^ 1) * 2560 + wo * 40 + wk8]),
                     wbase + (size_t)(mi * 64 + wo) * 192 + mc * 32 + wk8);
                cp_commit();
                cp_wait<1>();
            } else {
                cp_wait<0>();
            }
            __syncthreads();
            const int wsb = 25600 + buf * 2560;
            #pragma unroll
            for (int ks = 0; ks < 2; ks++) {
                uint32 a[4];
                ldsm4(a, sptr(&SM[wsb + (ob0 + aRow) * 40 + ks * 16 + aCol]));
                #pragma unroll
                for (int pr = 0; pr < 4; pr++) {
                    uint32 b[4];
                    ldsm4(b, sptr(&SM[(coff + pr * 16 + bRow) * 200 + c * 32 + ks * 16 + bCol]));
                    mmah(acc[2 * pr],     a, b[0], b[1]);
                    mmah(acc[2 * pr + 1], a, b[2], b[3]);
                }
            }
            __syncthreads();
        }

        // ---- epilogue for part i ----
        const int o0 = ha * 192 + i * 64;
        const int c0 = ob0 + r;
        const float ba = bias[o0 + c0], bb = bias[o0 + c0 + 8];
        if (i < 2) {  // Q or K -> qk16 channel-last
            #pragma unroll
            for (int nt = 0; nt < 8; nt++) {
                const int tok = coff + nt * 8 + 2 * tg;
                E[tok * 72 + c0]           = __float2half(acc[nt].x + ba);
                E[(tok + 1) * 72 + c0]     = __float2half(acc[nt].y + ba);
                E[tok * 72 + c0 + 8]       = __float2half(acc[nt].z + bb);
                E[(tok + 1) * 72 + c0 + 8] = __float2half(acc[nt].w + bb);
            }
            __syncthreads();
            const int base = ha * 128 + i * 64;
            #pragma unroll
            for (int ii = 0; ii < 4; ii++) {
                int j = tid + 256 * ii;
                int tok = j >> 3, seg = j & 7;
                *(uint4*)(outqk + (size_t)(g0 + tok) * 384 + base + seg * 8) =
                    *(const uint4*)(E + tok * 72 + seg * 8);
            }
        } else {      // V -> d-major
            #pragma unroll
            for (int nt = 0; nt < 8; nt++) {
                const int tok = coff + nt * 8 + 2 * tg;
                *(__half2*)(E + c0 * 136 + tok) =
                    __floats2half2_rn(acc[nt].x + ba, acc[nt].y + ba);
                *(__half2*)(E + (c0 + 8) * 136 + tok) =
                    __floats2half2_rn(acc[nt].z + bb, acc[nt].w + bb);
            }
            __syncthreads();
            const int cvb = ha * 64;
            #pragma unroll
            for (int ii = 0; ii < 4; ii++) {
                int j = tid + 256 * ii;
                int ch = j >> 4, seg = j & 15;
                int gt = g0 + seg * 8;
                int img = gt >> ls, tok = gt & Lm1;
                *(uint4*)(outv + ((size_t)img * 192 + cvb + ch) * L + tok) =
                    *(const uint4*)(E + ch * 136 + seg * 8);
            }
        }
        __syncthreads();
    }
}

// ---------------------------------------------------------------------------
// Proj conv, X-persistent, 256 threads, 3 o-parts, fp32 out + residual.
// smem halves: X [0,25600); W [25600,30720). 61,440 B.
// mode 1: res same layout; mode 2: res x-layout
// ---------------------------------------------------------------------------
#define CONVP_SMEM 61440

__global__ __launch_bounds__(256, 2) void k_convp(
    const __half* __restrict__ X, const __half* __restrict__ W,
    const float* __restrict__ bias, const float* __restrict__ res,
    float* __restrict__ outf, int ls, int mode) {
    extern __shared__ __half SM[];
    const int tid = threadIdx.x, lane = tid & 31, w = tid >> 5;
    const int r = lane >> 2, tg = lane & 3;
    const int g0 = blockIdx.x * 128;
    const int L = 1 << ls, Lm1 = L - 1;
    const int aRow = (lane & 7) + 8 * ((lane >> 3) & 1);
    const int aCol = 8 * (lane >> 4);
    const int bRow = (lane & 7) + 8 * (lane >> 4);
    const int bCol = 8 * ((lane >> 3) & 1);
    const int ob0 = (w >> 1) * 16, coff = (w & 1) * 64;
    const int wo = tid & 63, wk8 = (tid >> 6) * 8;

    {
        const int stok = tid >> 1, xh = (tid & 1) * 96;
        const __half* xsrc = X + (size_t)(g0 + stok) * 192 + xh;
        #pragma unroll
        for (int s = 0; s < 12; s++)
            cp16(sptr(&SM[stok * 200 + xh + s * 8]), xsrc + s * 8);
        cp_commit();
    }
    cp16(sptr(&SM[25600 + wo * 40 + wk8]), W + (size_t)wo * 192 + wk8);
    cp_commit();

    for (int i = 0; i < 3; i++) {
        float4 acc[8];
        #pragma unroll
        for (int nt = 0; nt < 8; nt++) acc[nt] = make_float4(0.f, 0.f, 0.f, 0.f);

        for (int c = 0; c < 6; c++) {
            const int m = i * 6 + c;
            const int buf = m & 1;
            if (m < 17) {
                const int mn = m + 1;
                const int mi = mn / 6, mc = mn - mi * 6;
                cp16(sptr(&SM[25600 + (buf ^ 1) * 2560 + wo * 40 + wk8]),
                     W + (size_t)(mi * 64 + wo) * 192 + mc * 32 + wk8);
                cp_commit();
                cp_wait<1>();
            } else {
                cp_wait<0>();
            }
            __syncthreads();
            const int wsb = 25600 + buf * 2560;
            #pragma unroll
            for (int ks = 0; ks < 2; ks++) {
                uint32 a[4];
                ldsm4(a, sptr(&SM[wsb + (ob0 + aRow) * 40 + ks * 16 + aCol]));
                #pragma unroll
                for (int pr = 0; pr < 4; pr++) {
                    uint32 b[4];
                    ldsm4(b, sptr(&SM[(coff + pr * 16 + bRow) * 200 + c * 32 + ks * 16 + bCol]));
                    mmah(acc[2 * pr],     a, b[0], b[1]);
                    mmah(acc[2 * pr + 1], a, b[2], b[3]);
                }
            }
            __syncthreads();
        }

        const int oa = i * 64 + ob0 + r;
        const int obr = oa + 8;
        const float ba = bias[oa], bb = bias[obr];
        #pragma unroll
        for (int nt = 0; nt < 8; nt++) {
            int g = g0 + coff + nt * 8 + 2 * tg;
            float vax = acc[nt].x + ba, vay = acc[nt].y + ba;
            float vbx = acc[nt].z + bb, vby = acc[nt].w + bb;
            int n = g >> ls, l = g & Lm1;
            size_t pAa = ((size_t)n * 192 + oa) * L + l;
            size_t pBb = ((size_t)n * 192 + obr) * L + l;
            float2 va = make_float2(vax, vay);
            float2 vb = make_float2(vbx, vby);
            if (mode == 1) {
                float2 qa = *(const float2*)(res + pAa);
                float2 qb = *(const float2*)(res + pBb);
                va.x += qa.x; va.y += qa.y; vb.x += qb.x; vb.y += qb.y;
            } else {
                int b = n >> 4, t = n & 15;
                size_t xa = (((size_t)(b * 192 + oa) * 16 + t) << 10) + l;
                size_t xb = (((size_t)(b * 192 + obr) * 16 + t) << 10) + l;
                float2 qa = *(const float2*)(res + xa);
                float2 qb = *(const float2*)(res + xb);
                va.x += qa.x; va.y += qa.y; vb.x += qb.x; vb.y += qb.y;
            }
            *(float2*)(outf + pAa) = va;
            *(float2*)(outf + pBb) = vb;
        }
        __syncthreads();
    }
}

// ---------------------------------------------------------------------------
// Attention pass 1: flash fp16 MMA + ldmatrix fragments.
// ---------------------------------------------------------------------------
#define HS 72

__global__ __launch_bounds__(128, 4) void k_attn1h(const __half* __restrict__ qk,
                                                   const __half* __restrict__ vT,
                                                   __half* __restrict__ outh) {
    __shared__ __align__(16) __half smh[4 * 64 * HS];
    __half* U  = smh;
    __half* K0 = smh + 64 * HS;
    __half* K1 = smh + 2 * 64 * HS;
    __half* Vt = smh + 3 * 64 * HS;

    const int tid = threadIdx.x, lane = tid & 31, w = tid >> 5;
    const int r = lane >> 2, tg = lane & 3;
    const int bh = blockIdx.y, n = bh / 3, h = bh % 3;
    const int q0 = blockIdx.x * 64;
    const __half* Qg = qk + ((size_t)(n * 1024) + q0) * 384 + h * 128;
    const __half* Kg = qk + (size_t)(n * 1024) * 384 + h * 128 + 64;
    const __half* Vg = vT + (size_t)(n * 192 + h * 64) * 1024;
    const int aRow = (lane & 7) + 8 * ((lane >> 3) & 1);
    const int aCol = 8 * (lane >> 4);
    const int bRow = (lane & 7) + 8 * (lane >> 4);
    const int bCol = 8 * ((lane >> 3) & 1);

    const int stok = tid >> 1, seg = (tid & 1) * 32;

    #pragma unroll
    for (int i = 0; i < 4; i++)
        cp16(sptr(&K0[stok * HS + seg + i * 8]), Kg + (size_t)stok * 384 + seg + i * 8);
    #pragma unroll
    for (int i = 0; i < 4; i++)
        cp16(sptr(&U[stok * HS + seg + i * 8]), Qg + (size_t)stok * 384 + seg + i * 8);
    cp_commit();
    cp_wait<0>();
    __syncthreads();

    uint32 qa[4][4];
    #pragma unroll
    for (int ks = 0; ks < 4; ks++)
        ldsm4(qa[ks], sptr(&U[(16 * w + aRow) * HS + ks * 16 + aCol]));

    float4 o[8];
    #pragma unroll
    for (int nt = 0; nt < 8; nt++) o[nt] = make_float4(0.f, 0.f, 0.f, 0.f);
    float m0 = -1e30f, m1 = -1e30f, s0 = 0.f, s1 = 0.f;
    __half* pr0h = U + (16 * w + r) * HS;
    __half* pr1h = U + (16 * w + r + 8) * HS;
    const float SC = 0.125f;

    for (int kt = 0; kt < 16; kt++) {
        const int buf = kt & 1;
        {
            const int sb = kt * 64;
            #pragma unroll
            for (int i = 0; i < 4; i++)
                cp16(sptr(&Vt[stok * HS + seg + i * 8]),
                     Vg + (size_t)stok * 1024 + sb + seg + i * 8);
            cp_commit();
        }
        if (kt < 15) {
            const int sb = (kt + 1) * 64;
            __half* Kn = buf ? K0 : K1;
            #pragma unroll
            for (int i = 0; i < 4; i++)
                cp16(sptr(&Kn[stok * HS + seg + i * 8]),
                     Kg + (size_t)(sb + stok) * 384 + seg + i * 8);
        }
        cp_commit();
        cp_wait<2>();
        __syncthreads();
        const __half* Ks = buf ? K1 : K0;

        float4 sc[8];
        #pragma unroll
        for (int nt = 0; nt < 8; nt++) sc[nt] = make_float4(0.f, 0.f, 0.f, 0.f);
        #pragma unroll
        for (int ks = 0; ks < 4; ks++) {
            #pragma unroll
            for (int pr = 0; pr < 4; pr++) {
                uint32 b[4];
                ldsm4(b, sptr(&Ks[(pr * 16 + bRow) * HS + ks * 16 + bCol]));
                mmah(sc[2 * pr],     qa[ks], b[0], b[1]);
                mmah(sc[2 * pr + 1], qa[ks], b[2], b[3]);
            }
        }

        float tm0 = -1e30f, tm1 = -1e30f;
        #pragma unroll
        for (int nt = 0; nt < 8; nt++) {
            tm0 = fmaxf(tm0, fmaxf(sc[nt].x, sc[nt].y));
            tm1 = fmaxf(tm1, fmaxf(sc[nt].z, sc[nt].w));
        }
        tm0 = fmaxf(tm0, __shfl_xor_sync(0xffffffffu, tm0, 1));
        tm0 = fmaxf(tm0, __shfl_xor_sync(0xffffffffu, tm0, 2));
        tm1 = fmaxf(tm1, __shfl_xor_sync(0xffffffffu, tm1, 1));
        tm1 = fmaxf(tm1, __shfl_xor_sync(0xffffffffu, tm1, 2));
        tm0 *= SC; tm1 *= SC;
        float nm0 = fmaxf(m0, tm0), nm1 = fmaxf(m1, tm1);
        float a0 = __expf(m0 - nm0), a1 = __expf(m1 - nm1);
        float t0 = 0.f, t1 = 0.f;
        #pragma unroll
        for (int nt = 0; nt < 8; nt++) {
            float px = __expf(fmaf(sc[nt].x, SC, -nm0));
            float py = __expf(fmaf(sc[nt].y, SC, -nm0));
            float pz = __expf(fmaf(sc[nt].z, SC, -nm1));
            float pw = __expf(fmaf(sc[nt].w, SC, -nm1));
            t0 += px + py; t1 += pz + pw;
            const int col = nt * 8 + 2 * tg;
            *(__half2*)(pr0h + col) = __floats2half2_rn(px, py);
            *(__half2*)(pr1h + col) = __floats2half2_rn(pz, pw);
            o[nt].x *= a0; o[nt].y *= a0;
            o[nt].z *= a1; o[nt].w *= a1;
        }
        t0 += __shfl_xor_sync(0xffffffffu, t0, 1);
        t0 += __shfl_xor_sync(0xffffffffu, t0, 2);
        t1 += __shfl_xor_sync(0xffffffffu, t1, 1);
        t1 += __shfl_xor_sync(0xffffffffu, t1, 2);
        s0 = s0 * a0 + t0;
        s1 = s1 * a1 + t1;
        m0 = nm0; m1 = nm1;
        __syncwarp();

        cp_wait<1>();
        __syncthreads();

        #pragma unroll
        for (int ks = 0; ks < 4; ks++) {
            uint32 a[4];
            ldsm4(a, sptr(&U[(16 * w + aRow) * HS + ks * 16 + aCol]));
            #pragma unroll
            for (int pr = 0; pr < 4; pr++) {
                uint32 b[4];
                ldsm4(b, sptr(&Vt[(pr * 16 + bRow) * HS + ks * 16 + bCol]));
                mmah(o[2 * pr],     a, b[0], b[1]);
                mmah(o[2 * pr + 1], a, b[2], b[3]);
            }
        }
        __syncthreads();
    }

    float i0 = 1.f / s0, i1 = 1.f / s1;
    __half* Os = K0;
    #pragma unroll
    for (int nt = 0; nt < 8; nt++) {
        const int col = nt * 8 + 2 * tg;
        *(__half2*)(Os + (16 * w + r) * HS + col)     = __floats2half2_rn(o[nt].x * i0, o[nt].y * i0);
        *(__half2*)(Os + (16 * w + r + 8) * HS + col) = __floats2half2_rn(o[nt].z * i1, o[nt].w * i1);
    }
    __syncthreads();
    __half* dst = outh + ((size_t)(n * 1024) + q0 + stok) * 192 + h * 64 + seg;
    #pragma unroll
    for (int i = 0; i < 4; i++)
        *(uint4*)(dst + i * 8) = *(const uint4*)(Os + stok * HS + seg + i * 8);
}

// ---------------------------------------------------------------------------
// Attention pass 2: L=16, scalar fp32 from half inputs
// ---------------------------------------------------------------------------
__global__ void k_attn2h(const __half* __restrict__ qkh, const __half* __restrict__ vTh,
                         __half* __restrict__ outh) {
    __shared__ float qs[16][68], ks[16][68], vs[1024], S[16 * 17];
    int bh = blockIdx.x, n = bh / 3, h = bh % 3;
    int tid = threadIdx.x;
    const __half* Qb = qkh + (size_t)(n * 16) * 384 + h * 128;
    const __half* Vb = vTh + (size_t)(n * 192 + h * 64) * 16;
    for (int i = tid; i < 1024; i += 256) {
        int q = i >> 6, c = i & 63;
        qs[q][c] = __half2float(Qb[(size_t)q * 384 + c]) * 0.125f;
        ks[q][c] = __half2float(Qb[(size_t)q * 384 + 64 + c]);
        vs[i] = __half2float(Vb[i]);
    }
    __syncthreads();
    {
        int q = tid >> 4, s = tid & 15;
        float a = 0.f;
        #pragma unroll
        for (int c = 0; c < 64; c++) a += qs[q][c] * ks[s][c];
        S[q * 17 + s] = a;
    }
    __syncthreads();
    if (tid < 16) {
        float* row = S + tid * 17;
        float m = -1e30f;
        #pragma unroll
        for (int s = 0; s < 16; s++) m = fmaxf(m, row[s]);
        float sum = 0.f;
        #pragma unroll
        for (int s = 0; s < 16; s++) { float e = __expf(row[s] - m); row[s] = e; sum += e; }
        float inv = 1.f / sum;
        #pragma unroll
        for (int s = 0; s < 16; s++) row[s] *= inv;
    }
    __syncthreads();
    {
        int q = tid & 15;
        int cb = (tid >> 4) << 2;
        float a0 = 0.f, a1 = 0.f, a2 = 0.f, a3 = 0.f;
        #pragma unroll
        for (int s = 0; s < 16; s++) {
            float sv = S[q * 17 + s];
            a0 += vs[(cb + 0) * 16 + s] * sv;
            a1 += vs[(cb + 1) * 16 + s] * sv;
            a2 += vs[(cb + 2) * 16 + s] * sv;
            a3 += vs[(cb + 3) * 16 + s] * sv;
        }
        __half* ob = outh + ((size_t)(n * 16) + q) * 192 + h * 64 + cb;
        ob[0] = __float2half(a0);
        ob[1] = __float2half(a1);
        ob[2] = __float2half(a2);
        ob[3] = __float2half(a3);
    }
}

// ---------------------------------------------------------------------------
extern "C" void kernel_launch(void* const* d_in, const int* in_sizes, int n_in,
                              void* d_out, int out_size) {
    const float* x       = (const float*)d_in[0];
    const float* norm_g  = (const float*)d_in[1];
    const float* norm_b  = (const float*)d_in[2];
    const float* qkv_w   = (const float*)d_in[3];
    const float* qkv_b   = (const float*)d_in[4];
    const float* proj_w  = (const float*)d_in[5];
    const float* proj_b  = (const float*)d_in[6];
    const float* normt_g = (const float*)d_in[7];
    const float* normt_b = (const float*)d_in[8];
    const float* qkvt_w  = (const float*)d_in[9];
    const float* qkvt_b  = (const float*)d_in[10];
    const float* projt_w = (const float*)d_in[11];
    const float* projt_b = (const float*)d_in[12];
    float* out = (float*)d_out;

    float *xs, *y, *yt;
    __half *nrm16, *qk16, *v16T, *att16, *w16;
    cudaGetSymbolAddress((void**)&xs,    g_xs);
    cudaGetSymbolAddress((void**)&y,     g_y);
    cudaGetSymbolAddress((void**)&yt,    g_yt);
    cudaGetSymbolAddress((void**)&nrm16, g_nrm16);
    cudaGetSymbolAddress((void**)&qk16,  g_qk16);
    cudaGetSymbolAddress((void**)&v16T,  g_v16T);
    cudaGetSymbolAddress((void**)&att16, g_att16);
    cudaGetSymbolAddress((void**)&w16,   g_w16);

    const __half* w_qkv  = w16;
    const __half* w_proj = w16 + 110592;
    const __half* w_qkvt = w16 + 147456;
    const __half* w_projt= w16 + 258048;

    cudaFuncSetAttribute(k_convq, cudaFuncAttributeMaxDynamicSharedMemorySize, CONVQ_SMEM);
    cudaFuncSetAttribute(k_convp, cudaFuncAttributeMaxDynamicSharedMemorySize, CONVP_SMEM);

    k_wprep<<<288, 1024>>>(qkv_w, proj_w, qkvt_w, projt_w);

    // ---- pass 1 (spatial, L=1024) ----
    k_gn1s<<<NBT * 32, 256>>>(x);
    k_gn1at<<<dim3(16, 32), 256>>>(x, norm_g, norm_b);
    k_convq<<<dim3(256, 3), 256, CONVQ_SMEM>>>(nrm16, w_qkv, qkv_b, qk16, v16T, 10);
    k_attn1h<<<dim3(16, 96), 128>>>(qk16, v16T, att16);
    k_convp<<<256, 256, CONVP_SMEM>>>(att16, w_proj, proj_b, x, y, 10, 2);

    // ---- pass 2 (temporal, L=16) ----
    k_transpose2c<<<dim3(16, 48, 2), 256>>>();
    k_gn2h<<<2048, 128>>>(yt, normt_g, normt_b, nrm16);
    k_convq<<<dim3(256, 3), 256, CONVQ_SMEM>>>(nrm16, w_qkvt, qkvt_b, qk16, v16T, 4);
    k_attn2h<<<6144, 256>>>(qk16, v16T, att16);
    k_convp<<<256, 256, CONVP_SMEM>>>(att16, w_projt, projt_b, yt, xs, 4, 1);
    k_transpose3c<<<dim3(16, 48, 2), 256>>>(out);
}

// round 16
// speedup vs baseline: 1.0783x; 1.0783x over previous
#include <cuda_runtime.h>
#include <cuda_fp16.h>
#include <math.h>

#define NBT 32
#define CCH 192
#define TOT (NBT*CCH*1024)
typedef unsigned int uint32;

// fp32 scratch
__device__ float g_xs [TOT];          // z (bhw,c,t) in pass2
__device__ float g_y  [TOT];
__device__ float g_yt [TOT];
__device__ float g_stat[NBT*32*2];
// fp16 scratch
__device__ __half g_nrm16[32768*192];
__device__ __half g_qk16 [32768*384];
__device__ __half g_v16T [32768*192];
__device__ __half g_att16[32768*192];
__device__ __half g_w16  [294912];

// ---- helpers ----------------------------------------------------------------
__device__ __forceinline__ void mmah(float4 &c, const uint32* a, uint32 b0, uint32 b1) {
    asm("mma.sync.aligned.m16n8k16.row.col.f32.f16.f16.f32 "
        "{%0,%1,%2,%3},{%4,%5,%6,%7},{%8,%9},{%0,%1,%2,%3};"
        : "+f"(c.x), "+f"(c.y), "+f"(c.z), "+f"(c.w)
        : "r"(a[0]), "r"(a[1]), "r"(a[2]), "r"(a[3]), "r"(b0), "r"(b1));
}
__device__ __forceinline__ uint32 sptr(const void* p) {
    return (uint32)__cvta_generic_to_shared(p);
}
__device__ __forceinline__ void ldsm4(uint32* r, uint32 addr) {
    asm volatile("ldmatrix.sync.aligned.m8n8.x4.shared.b16 {%0,%1,%2,%3}, [%4];"
        : "=r"(r[0]), "=r"(r[1]), "=r"(r[2]), "=r"(r[3]) : "r"(addr));
}
__device__ __forceinline__ void cp16(uint32 s, const void* g) {
    asm volatile("cp.async.ca.shared.global [%0], [%1], 16;" :: "r"(s), "l"(g));
}
__device__ __forceinline__ void cp_commit() { asm volatile("cp.async.commit_group;"); }
template<int N> __device__ __forceinline__ void cp_wait() {
    asm volatile("cp.async.wait_group %0;" :: "n"(N));
}

// ---------------------------------------------------------------------------
// Weight fp16 prep
// ---------------------------------------------------------------------------
__global__ void k_wprep(const float* __restrict__ qw, const float* __restrict__ pw,
                        const float* __restrict__ qtw, const float* __restrict__ ptw) {
    int i = blockIdx.x * 1024 + threadIdx.x;
    float v;
    if      (i < 110592) v = qw[i];
    else if (i < 147456) v = pw[i - 110592];
    else if (i < 258048) v = qtw[i - 147456];
    else                 v = ptw[i - 258048];
    g_w16[i] = __float2half(v);
}

// ---------------------------------------------------------------------------
// GroupNorm pass 1 stats
// ---------------------------------------------------------------------------
__global__ void k_gn1s(const float* __restrict__ x) {
    int n = blockIdx.x >> 5, g = blockIdx.x & 31;
    int b = n >> 4, t = n & 15;
    const float* xb = x + (((size_t)(b * CCH + g * 6) * 16 + t) << 10);
    int tid = threadIdx.x;
    float s = 0.f, q = 0.f;
    for (int i = tid; i < 6144; i += 256) {
        float v = xb[((size_t)(i >> 10) << 14) + (i & 1023)];
        s += v; q += v * v;
    }
    __shared__ float rs[256], rq[256];
    rs[tid] = s; rq[tid] = q;
    __syncthreads();
    for (int st = 128; st > 0; st >>= 1) {
        if (tid < st) { rs[tid] += rs[tid + st]; rq[tid] += rq[tid + st]; }
        __syncthreads();
    }
    if (tid == 0) {
        float mean = rs[0] / 6144.f;
        float var  = rq[0] / 6144.f - mean * mean;
        g_stat[blockIdx.x * 2]     = mean;
        g_stat[blockIdx.x * 2 + 1] = rsqrtf(var + 1e-5f);
    }
}

// ---------------------------------------------------------------------------
// GroupNorm pass 1 apply, tiled coalesced
// ---------------------------------------------------------------------------
__global__ __launch_bounds__(256) void k_gn1at(const float* __restrict__ x,
                                               const float* __restrict__ gam,
                                               const float* __restrict__ bet) {
    __shared__ __half sbuf[64 * 200];
    const int hw0 = blockIdx.x * 64, bt = blockIdx.y;
    const int b = bt >> 4, t = bt & 15;
    const int tid = threadIdx.x;
    #pragma unroll
    for (int rep = 0; rep < 3; rep++) {
        const int c = rep * 64 + (tid >> 2);
        const int hwq = (tid & 3) * 16;
        const int g = c / 6;
        const float mu = g_stat[(bt * 32 + g) * 2];
        const float iv = g_stat[(bt * 32 + g) * 2 + 1];
        const float ga = gam[c] * iv;
        const float be = bet[c] - mu * ga;
        const float* src = x + (((size_t)(b * CCH + c) * 16 + t) << 10) + hw0 + hwq;
        #pragma unroll
        for (int j = 0; j < 16; j += 4) {
            float4 v = *(const float4*)(src + j);
            sbuf[(hwq + j + 0) * 200 + c] = __float2half(v.x * ga + be);
            sbuf[(hwq + j + 1) * 200 + c] = __float2half(v.y * ga + be);
            sbuf[(hwq + j + 2) * 200 + c] = __float2half(v.z * ga + be);
            sbuf[(hwq + j + 3) * 200 + c] = __float2half(v.w * ga + be);
        }
    }
    __syncthreads();
    #pragma unroll
    for (int i = tid; i < 1536; i += 256) {
        int tok = i / 24, seg = i - tok * 24;
        *(uint4*)(g_nrm16 + ((size_t)(bt * 1024 + hw0 + tok)) * 192 + seg * 8) =
            *(const uint4*)(sbuf + tok * 200 + seg * 8);
    }
}

// ---------------------------------------------------------------------------
// GroupNorm pass 2
// ---------------------------------------------------------------------------
__global__ void k_gn2h(const float* __restrict__ X, const float* __restrict__ gam,
                       const float* __restrict__ bet, __half* __restrict__ out16) {
    int n = blockIdx.x;
    __shared__ float buf[3072];
    __shared__ float mu[32], iv[32];
    int tid = threadIdx.x;
    const float4* xb = (const float4*)(X + (size_t)n * 3072);
    for (int i = tid; i < 768; i += 128) ((float4*)buf)[i] = xb[i];
    __syncthreads();
    int w = tid >> 5, lane = tid & 31;
    for (int g = w; g < 32; g += 4) {
        float v0 = buf[g * 96 + lane], v1 = buf[g * 96 + 32 + lane], v2 = buf[g * 96 + 64 + lane];
        float s = v0 + v1 + v2, q = v0 * v0 + v1 * v1 + v2 * v2;
        #pragma unroll
        for (int off = 16; off; off >>= 1) {
            s += __shfl_xor_sync(0xffffffffu, s, off);
            q += __shfl_xor_sync(0xffffffffu, q, off);
        }
        if (lane == 0) {
            float m = s / 96.f, va = q / 96.f - m * m;
            mu[g] = m; iv[g] = rsqrtf(va + 1e-5f);
        }
    }
    __syncthreads();
    __half* ob = out16 + (size_t)n * 3072;
    for (int j = tid; j < 3072; j += 128) {
        int t = j / 192, c = j - t * 192;
        int g = c / 6;
        ob[j] = __float2half((buf[c * 16 + t] - mu[g]) * iv[g] * gam[c] + bet[c]);
    }
}

// ---------------------------------------------------------------------------
// c-blocked transposes
// ---------------------------------------------------------------------------
__global__ __launch_bounds__(256) void k_transpose2c() {  // y (bt,c,hw) -> yt (bhw,c,t)
    __shared__ float sb[5168];
    const int hw0 = blockIdx.x * 64, c0 = blockIdx.y * 4, b = blockIdx.z;
    const int tid = threadIdx.x, w = tid >> 5, lane = tid & 31;
    #pragma unroll
    for (int it = 0; it < 8; it++) {
        int p = it * 8 + w;
        int c = p >> 4, t = p & 15;
        float2 v = *(const float2*)&g_y[(((size_t)(b * 16 + t) * CCH + c0 + c) << 10)
                                        + hw0 + lane * 2];
        sb[c * 1296 + (lane * 2) * 20 + t]     = v.x;
        sb[c * 1296 + (lane * 2 + 1) * 20 + t] = v.y;
    }
    __syncthreads();
    #pragma unroll
    for (int i2 = 0; i2 < 4; i2++) {
        int u = tid + 256 * i2;
        int hw = u >> 4, q = u & 15;
        int c = q >> 2, t4 = (q & 3) * 4;
        *(float4*)&g_yt[((size_t)(b * 1024 + hw0 + hw) * CCH + c0 + c) * 16 + t4] =
            *(const float4*)&sb[c * 1296 + hw * 20 + t4];
    }
}

__global__ __launch_bounds__(256) void k_transpose3c(float* __restrict__ out) {
    __shared__ float sb[5168];
    const int hw0 = blockIdx.x * 64, c0 = blockIdx.y * 4, b = blockIdx.z;
    const int tid = threadIdx.x, w = tid >> 5, lane = tid & 31;
    #pragma unroll
    for (int i2 = 0; i2 < 4; i2++) {
        int u = tid + 256 * i2;
        int hw = u >> 4, q = u & 15;
        int c = q >> 2, t4 = (q & 3) * 4;
        *(float4*)&sb[c * 1296 + hw * 20 + t4] =
            *(const float4*)&g_xs[((size_t)(b * 1024 + hw0 + hw) * CCH + c0 + c) * 16 + t4];
    }
    __syncthreads();
    #pragma unroll
    for (int it = 0; it < 8; it++) {
        int p = it * 8 + w;
        int c = p >> 4, t = p & 15;
        float2 v = make_float2(sb[c * 1296 + (lane * 2) * 20 + t],
                               sb[c * 1296 + (lane * 2 + 1) * 20 + t]);
        *(float2*)&out[(((size_t)(b * CCH + c0 + c) * 16 + t) << 10) + hw0 + lane * 2] = v;
    }
}

// ---------------------------------------------------------------------------
// QKV conv: X-persistent + W-part-resident (barrier-free inner loop).
// Grid (tokenTiles, 3 heads), 256 thr / 8 warps, warp tile 16o x 64tok.
// smem halves: X [0,25600) t*200+k; W [25600,40960) c*2560+o*40+k;
//              E [40960,50176). 100,352 B -> 2 CTAs/SM.
// Per part: 1 W stage + 1 sync, then 6 chunks pure LDSM+MMA.
// ---------------------------------------------------------------------------
#define CONVQ_SMEM 100352

__global__ __launch_bounds__(256, 2) void k_convq(
    const __half* __restrict__ X, const __half* __restrict__ W,
    const float* __restrict__ bias,
    __half* __restrict__ outqk, __half* __restrict__ outv, int ls) {
    extern __shared__ __half SM[];
    const int tid = threadIdx.x, lane = tid & 31, w = tid >> 5;
    const int r = lane >> 2, tg = lane & 3;
    const int g0 = blockIdx.x * 128, ha = blockIdx.y;
    const int L = 1 << ls, Lm1 = L - 1;
    const int aRow = (lane & 7) + 8 * ((lane >> 3) & 1);
    const int aCol = 8 * (lane >> 4);
    const int bRow = (lane & 7) + 8 * (lane >> 4);
    const int bCol = 8 * ((lane >> 3) & 1);
    const int ob0 = (w >> 1) * 16, coff = (w & 1) * 64;
    const __half* wbase = W + (size_t)(ha * 192) * 192;
    __half* E = SM + 40960;

    // stage entire X tile (group 0)
    {
        const int stok = tid >> 1, xh = (tid & 1) * 96;
        const __half* xsrc = X + (size_t)(g0 + stok) * 192 + xh;
        #pragma unroll
        for (int s = 0; s < 12; s++)
            cp16(sptr(&SM[stok * 200 + xh + s * 8]), xsrc + s * 8);
        cp_commit();
    }

    for (int i = 0; i < 3; i++) {
        // stage whole W part i: 6 chunks x [64][40] (k 0..31 valid)
        #pragma unroll
        for (int s = 0; s < 6; s++) {
            int u = tid + 256 * s;
            int c = u >> 8, rem = u & 255;
            int o = rem >> 2, k8 = (rem & 3) * 8;
            cp16(sptr(&SM[25600 + c * 2560 + o * 40 + k8]),
                 wbase + (size_t)(i * 64 + o) * 192 + c * 32 + k8);
        }
        cp_commit();
        cp_wait<0>();
        __syncthreads();

        float4 acc[8];
        #pragma unroll
        for (int nt = 0; nt < 8; nt++) acc[nt] = make_float4(0.f, 0.f, 0.f, 0.f);

        // barrier-free inner loop over 6 chunks
        #pragma unroll
        for (int c = 0; c < 6; c++) {
            const int wsb = 25600 + c * 2560;
            #pragma unroll
            for (int ks = 0; ks < 2; ks++) {
                uint32 a[4];
                ldsm4(a, sptr(&SM[wsb + (ob0 + aRow) * 40 + ks * 16 + aCol]));
                #pragma unroll
                for (int pr = 0; pr < 4; pr++) {
                    uint32 b[4];
                    ldsm4(b, sptr(&SM[(coff + pr * 16 + bRow) * 200 + c * 32 + ks * 16 + bCol]));
                    mmah(acc[2 * pr],     a, b[0], b[1]);
                    mmah(acc[2 * pr + 1], a, b[2], b[3]);
                }
            }
        }

        // ---- epilogue for part i ----
        const int o0 = ha * 192 + i * 64;
        const int c0 = ob0 + r;
        const float ba = bias[o0 + c0], bb = bias[o0 + c0 + 8];
        if (i < 2) {  // Q or K -> qk16 channel-last
            #pragma unroll
            for (int nt = 0; nt < 8; nt++) {
                const int tok = coff + nt * 8 + 2 * tg;
                E[tok * 72 + c0]           = __float2half(acc[nt].x + ba);
                E[(tok + 1) * 72 + c0]     = __float2half(acc[nt].y + ba);
                E[tok * 72 + c0 + 8]       = __float2half(acc[nt].z + bb);
                E[(tok + 1) * 72 + c0 + 8] = __float2half(acc[nt].w + bb);
            }
            __syncthreads();
            const int base = ha * 128 + i * 64;
            #pragma unroll
            for (int ii = 0; ii < 4; ii++) {
                int j = tid + 256 * ii;
                int tok = j >> 3, seg = j & 7;
                *(uint4*)(outqk + (size_t)(g0 + tok) * 384 + base + seg * 8) =
                    *(const uint4*)(E + tok * 72 + seg * 8);
            }
        } else {      // V -> d-major
            #pragma unroll
            for (int nt = 0; nt < 8; nt++) {
                const int tok = coff + nt * 8 + 2 * tg;
                *(__half2*)(E + c0 * 136 + tok) =
                    __floats2half2_rn(acc[nt].x + ba, acc[nt].y + ba);
                *(__half2*)(E + (c0 + 8) * 136 + tok) =
                    __floats2half2_rn(acc[nt].z + bb, acc[nt].w + bb);
            }
            __syncthreads();
            const int cvb = ha * 64;
            #pragma unroll
            for (int ii = 0; ii < 4; ii++) {
                int j = tid + 256 * ii;
                int ch = j >> 4, seg = j & 15;
                int gt = g0 + seg * 8;
                int img = gt >> ls, tok = gt & Lm1;
                *(uint4*)(outv + ((size_t)img * 192 + cvb + ch) * L + tok) =
                    *(const uint4*)(E + ch * 136 + seg * 8);
            }
        }
        __syncthreads();
    }
}

// ---------------------------------------------------------------------------
// Proj conv: X-persistent + W-part-resident, fp32 out + residual.
// smem halves: X [0,25600); W [25600,40960). 81,920 B -> 2 CTAs/SM.
// mode 1: res same layout; mode 2: res x-layout
// ---------------------------------------------------------------------------
#define CONVP_SMEM 81920

__global__ __launch_bounds__(256, 2) void k_convp(
    const __half* __restrict__ X, const __half* __restrict__ W,
    const float* __restrict__ bias, const float* __restrict__ res,
    float* __restrict__ outf, int ls, int mode) {
    extern __shared__ __half SM[];
    const int tid = threadIdx.x, lane = tid & 31, w = tid >> 5;
    const int r = lane >> 2, tg = lane & 3;
    const int g0 = blockIdx.x * 128;
    const int L = 1 << ls, Lm1 = L - 1;
    const int aRow = (lane & 7) + 8 * ((lane >> 3) & 1);
    const int aCol = 8 * (lane >> 4);
    const int bRow = (lane & 7) + 8 * (lane >> 4);
    const int bCol = 8 * ((lane >> 3) & 1);
    const int ob0 = (w >> 1) * 16, coff = (w & 1) * 64;

    {
        const int stok = tid >> 1, xh = (tid & 1) * 96;
        const __half* xsrc = X + (size_t)(g0 + stok) * 192 + xh;
        #pragma unroll
        for (int s = 0; s < 12; s++)
            cp16(sptr(&SM[stok * 200 + xh + s * 8]), xsrc + s * 8);
        cp_commit();
    }

    for (int i = 0; i < 3; i++) {
        #pragma unroll
        for (int s = 0; s < 6; s++) {
            int u = tid + 256 * s;
            int c = u >> 8, rem = u & 255;
            int o = rem >> 2, k8 = (rem & 3) * 8;
            cp16(sptr(&SM[25600 + c * 2560 + o * 40 + k8]),
                 W + (size_t)(i * 64 + o) * 192 + c * 32 + k8);
        }
        cp_commit();
        cp_wait<0>();
        __syncthreads();

        float4 acc[8];
        #pragma unroll
        for (int nt = 0; nt < 8; nt++) acc[nt] = make_float4(0.f, 0.f, 0.f, 0.f);

        #pragma unroll
        for (int c = 0; c < 6; c++) {
            const int wsb = 25600 + c * 2560;
            #pragma unroll
            for (int ks = 0; ks < 2; ks++) {
                uint32 a[4];
                ldsm4(a, sptr(&SM[wsb + (ob0 + aRow) * 40 + ks * 16 + aCol]));
                #pragma unroll
                for (int pr = 0; pr < 4; pr++) {
                    uint32 b[4];
                    ldsm4(b, sptr(&SM[(coff + pr * 16 + bRow) * 200 + c * 32 + ks * 16 + bCol]));
                    mmah(acc[2 * pr],     a, b[0], b[1]);
                    mmah(acc[2 * pr + 1], a, b[2], b[3]);
                }
            }
        }

        const int oa = i * 64 + ob0 + r;
        const int obr = oa + 8;
        const float ba = bias[oa], bb = bias[obr];
        #pragma unroll
        for (int nt = 0; nt < 8; nt++) {
            int g = g0 + coff + nt * 8 + 2 * tg;
            float vax = acc[nt].x + ba, vay = acc[nt].y + ba;
            float vbx = acc[nt].z + bb, vby = acc[nt].w + bb;
            int n = g >> ls, l = g & Lm1;
            size_t pAa = ((size_t)n * 192 + oa) * L + l;
            size_t pBb = ((size_t)n * 192 + obr) * L + l;
            float2 va = make_float2(vax, vay);
            float2 vb = make_float2(vbx, vby);
            if (mode == 1) {
                float2 qa = *(const float2*)(res + pAa);
                float2 qb = *(const float2*)(res + pBb);
                va.x += qa.x; va.y += qa.y; vb.x += qb.x; vb.y += qb.y;
            } else {
                int b = n >> 4, t = n & 15;
                size_t xa = (((size_t)(b * 192 + oa) * 16 + t) << 10) + l;
                size_t xb = (((size_t)(b * 192 + obr) * 16 + t) << 10) + l;
                float2 qa = *(const float2*)(res + xa);
                float2 qb = *(const float2*)(res + xb);
                va.x += qa.x; va.y += qa.y; vb.x += qb.x; vb.y += qb.y;
            }
            *(float2*)(outf + pAa) = va;
            *(float2*)(outf + pBb) = vb;
        }
        __syncthreads();
    }
}

// ---------------------------------------------------------------------------
// Attention pass 1: flash fp16 MMA + ldmatrix fragments.
// ---------------------------------------------------------------------------
#define HS 72

__global__ __launch_bounds__(128, 4) void k_attn1h(const __half* __restrict__ qk,
                                                   const __half* __restrict__ vT,
                                                   __half* __restrict__ outh) {
    __shared__ __align__(16) __half smh[4 * 64 * HS];
    __half* U  = smh;
    __half* K0 = smh + 64 * HS;
    __half* K1 = smh + 2 * 64 * HS;
    __half* Vt = smh + 3 * 64 * HS;

    const int tid = threadIdx.x, lane = tid & 31, w = tid >> 5;
    const int r = lane >> 2, tg = lane & 3;
    const int bh = blockIdx.y, n = bh / 3, h = bh % 3;
    const int q0 = blockIdx.x * 64;
    const __half* Qg = qk + ((size_t)(n * 1024) + q0) * 384 + h * 128;
    const __half* Kg = qk + (size_t)(n * 1024) * 384 + h * 128 + 64;
    const __half* Vg = vT + (size_t)(n * 192 + h * 64) * 1024;
    const int aRow = (lane & 7) + 8 * ((lane >> 3) & 1);
    const int aCol = 8 * (lane >> 4);
    const int bRow = (lane & 7) + 8 * (lane >> 4);
    const int bCol = 8 * ((lane >> 3) & 1);

    const int stok = tid >> 1, seg = (tid & 1) * 32;

    #pragma unroll
    for (int i = 0; i < 4; i++)
        cp16(sptr(&K0[stok * HS + seg + i * 8]), Kg + (size_t)stok * 384 + seg + i * 8);
    #pragma unroll
    for (int i = 0; i < 4; i++)
        cp16(sptr(&U[stok * HS + seg + i * 8]), Qg + (size_t)stok * 384 + seg + i * 8);
    cp_commit();
    cp_wait<0>();
    __syncthreads();

    uint32 qa[4][4];
    #pragma unroll
    for (int ks = 0; ks < 4; ks++)
        ldsm4(qa[ks], sptr(&U[(16 * w + aRow) * HS + ks * 16 + aCol]));

    float4 o[8];
    #pragma unroll
    for (int nt = 0; nt < 8; nt++) o[nt] = make_float4(0.f, 0.f, 0.f, 0.f);
    float m0 = -1e30f, m1 = -1e30f, s0 = 0.f, s1 = 0.f;
    __half* pr0h = U + (16 * w + r) * HS;
    __half* pr1h = U + (16 * w + r + 8) * HS;
    const float SC = 0.125f;

    for (int kt = 0; kt < 16; kt++) {
        const int buf = kt & 1;
        {
            const int sb = kt * 64;
            #pragma unroll
            for (int i = 0; i < 4; i++)
                cp16(sptr(&Vt[stok * HS + seg + i * 8]),
                     Vg + (size_t)stok * 1024 + sb + seg + i * 8);
            cp_commit();
        }
        if (kt < 15) {
            const int sb = (kt + 1) * 64;
            __half* Kn = buf ? K0 : K1;
            #pragma unroll
            for (int i = 0; i < 4; i++)
                cp16(sptr(&Kn[stok * HS + seg + i * 8]),
                     Kg + (size_t)(sb + stok) * 384 + seg + i * 8);
        }
        cp_commit();
        cp_wait<2>();
        __syncthreads();
        const __half* Ks = buf ? K1 : K0;

        float4 sc[8];
        #pragma unroll
        for (int nt = 0; nt < 8; nt++) sc[nt] = make_float4(0.f, 0.f, 0.f, 0.f);
        #pragma unroll
        for (int ks = 0; ks < 4; ks++) {
            #pragma unroll
            for (int pr = 0; pr < 4; pr++) {
                uint32 b[4];
                ldsm4(b, sptr(&Ks[(pr * 16 + bRow) * HS + ks * 16 + bCol]));
                mmah(sc[2 * pr],     qa[ks], b[0], b[1]);
                mmah(sc[2 * pr + 1], qa[ks], b[2], b[3]);
            }
        }

        float tm0 = -1e30f, tm1 = -1e30f;
        #pragma unroll
        for (int nt = 0; nt < 8; nt++) {
            tm0 = fmaxf(tm0, fmaxf(sc[nt].x, sc[nt].y));
            tm1 = fmaxf(tm1, fmaxf(sc[nt].z, sc[nt].w));
        }
        tm0 = fmaxf(tm0, __shfl_xor_sync(0xffffffffu, tm0, 1));
        tm0 = fmaxf(tm0, __shfl_xor_sync(0xffffffffu, tm0, 2));
        tm1 = fmaxf(tm1, __shfl_xor_sync(0xffffffffu, tm1, 1));
        tm1 = fmaxf(tm1, __shfl_xor_sync(0xffffffffu, tm1, 2));
        tm0 *= SC; tm1 *= SC;
        float nm0 = fmaxf(m0, tm0), nm1 = fmaxf(m1, tm1);
        float a0 = __expf(m0 - nm0), a1 = __expf(m1 - nm1);
        float t0 = 0.f, t1 = 0.f;
        #pragma unroll
        for (int nt = 0; nt < 8; nt++) {
            float px = __expf(fmaf(sc[nt].x, SC, -nm0));
            float py = __expf(fmaf(sc[nt].y, SC, -nm0));
            float pz = __expf(fmaf(sc[nt].z, SC, -nm1));
            float pw = __expf(fmaf(sc[nt].w, SC, -nm1));
            t0 += px + py; t1 += pz + pw;
            const int col = nt * 8 + 2 * tg;
            *(__half2*)(pr0h + col) = __floats2half2_rn(px, py);
            *(__half2*)(pr1h + col) = __floats2half2_rn(pz, pw);
            o[nt].x *= a0; o[nt].y *= a0;
            o[nt].z *= a1; o[nt].w *= a1;
        }
        t0 += __shfl_xor_sync(0xffffffffu, t0, 1);
        t0 += __shfl_xor_sync(0xffffffffu, t0, 2);
        t1 += __shfl_xor_sync(0xffffffffu, t1, 1);
        t1 += __shfl_xor_sync(0xffffffffu, t1, 2);
        s0 = s0 * a0 + t0;
        s1 = s1 * a1 + t1;
        m0 = nm0; m1 = nm1;
        __syncwarp();

        cp_wait<1>();
        __syncthreads();

        #pragma unroll
        for (int ks = 0; ks < 4; ks++) {
            uint32 a[4];
            ldsm4(a, sptr(&U[(16 * w + aRow) * HS + ks * 16 + aCol]));
            #pragma unroll
            for (int pr = 0; pr < 4; pr++) {
                uint32 b[4];
                ldsm4(b, sptr(&Vt[(pr * 16 + bRow) * HS + ks * 16 + bCol]));
                mmah(o[2 * pr],     a, b[0], b[1]);
                mmah(o[2 * pr + 1], a, b[2], b[3]);
            }
        }
        __syncthreads();
    }

    float i0 = 1.f / s0, i1 = 1.f / s1;
    __half* Os = K0;
    #pragma unroll
    for (int nt = 0; nt < 8; nt++) {
        const int col = nt * 8 + 2 * tg;
        *(__half2*)(Os + (16 * w + r) * HS + col)     = __floats2half2_rn(o[nt].x * i0, o[nt].y * i0);
        *(__half2*)(Os + (16 * w + r + 8) * HS + col) = __floats2half2_rn(o[nt].z * i1, o[nt].w * i1);
    }
    __syncthreads();
    __half* dst = outh + ((size_t)(n * 1024) + q0 + stok) * 192 + h * 64 + seg;
    #pragma unroll
    for (int i = 0; i < 4; i++)
        *(uint4*)(dst + i * 8) = *(const uint4*)(Os + stok * HS + seg + i * 8);
}

// ---------------------------------------------------------------------------
// Attention pass 2: L=16, scalar fp32 from half inputs
// ---------------------------------------------------------------------------
__global__ void k_attn2h(const __half* __restrict__ qkh, const __half* __restrict__ vTh,
                         __half* __restrict__ outh) {
    __shared__ float qs[16][68], ks[16][68], vs[1024], S[16 * 17];
    int bh = blockIdx.x, n = bh / 3, h = bh % 3;
    int tid = threadIdx.x;
    const __half* Qb = qkh + (size_t)(n * 16) * 384 + h * 128;
    const __half* Vb = vTh + (size_t)(n * 192 + h * 64) * 16;
    for (int i = tid; i < 1024; i += 256) {
        int q = i >> 6, c = i & 63;
        qs[q][c] = __half2float(Qb[(size_t)q * 384 + c]) * 0.125f;
        ks[q][c] = __half2float(Qb[(size_t)q * 384 + 64 + c]);
        vs[i] = __half2float(Vb[i]);
    }
    __syncthreads();
    {
        int q = tid >> 4, s = tid & 15;
        float a = 0.f;
        #pragma unroll
        for (int c = 0; c < 64; c++) a += qs[q][c] * ks[s][c];
        S[q * 17 + s] = a;
    }
    __syncthreads();
    if (tid < 16) {
        float* row = S + tid * 17;
        float m = -1e30f;
        #pragma unroll
        for (int s = 0; s < 16; s++) m = fmaxf(m, row[s]);
        float sum = 0.f;
        #pragma unroll
        for (int s = 0; s < 16; s++) { float e = __expf(row[s] - m); row[s] = e; sum += e; }
        float inv = 1.f / sum;
        #pragma unroll
        for (int s = 0; s < 16; s++) row[s] *= inv;
    }
    __syncthreads();
    {
        int q = tid & 15;
        int cb = (tid >> 4) << 2;
        float a0 = 0.f, a1 = 0.f, a2 = 0.f, a3 = 0.f;
        #pragma unroll
        for (int s = 0; s < 16; s++) {
            float sv = S[q * 17 + s];
            a0 += vs[(cb + 0) * 16 + s] * sv;
            a1 += vs[(cb + 1) * 16 + s] * sv;
            a2 += vs[(cb + 2) * 16 + s] * sv;
            a3 += vs[(cb + 3) * 16 + s] * sv;
        }
        __half* ob = outh + ((size_t)(n * 16) + q) * 192 + h * 64 + cb;
        ob[0] = __float2half(a0);
        ob[1] = __float2half(a1);
        ob[2] = __float2half(a2);
        ob[3] = __float2half(a3);
    }
}

// ---------------------------------------------------------------------------
extern "C" void kernel_launch(void* const* d_in, const int* in_sizes, int n_in,
                              void* d_out, int out_size) {
    const float* x       = (const float*)d_in[0];
    const float* norm_g  = (const float*)d_in[1];
    const float* norm_b  = (const float*)d_in[2];
    const float* qkv_w   = (const float*)d_in[3];
    const float* qkv_b   = (const float*)d_in[4];
    const float* proj_w  = (const float*)d_in[5];
    const float* proj_b  = (const float*)d_in[6];
    const float* normt_g = (const float*)d_in[7];
    const float* normt_b = (const float*)d_in[8];
    const float* qkvt_w  = (const float*)d_in[9];
    const float* qkvt_b  = (const float*)d_in[10];
    const float* projt_w = (const float*)d_in[11];
    const float* projt_b = (const float*)d_in[12];
    float* out = (float*)d_out;

    float *xs, *y, *yt;
    __half *nrm16, *qk16, *v16T, *att16, *w16;
    cudaGetSymbolAddress((void**)&xs,    g_xs);
    cudaGetSymbolAddress((void**)&y,     g_y);
    cudaGetSymbolAddress((void**)&yt,    g_yt);
    cudaGetSymbolAddress((void**)&nrm16, g_nrm16);
    cudaGetSymbolAddress((void**)&qk16,  g_qk16);
    cudaGetSymbolAddress((void**)&v16T,  g_v16T);
    cudaGetSymbolAddress((void**)&att16, g_att16);
    cudaGetSymbolAddress((void**)&w16,   g_w16);

    const __half* w_qkv  = w16;
    const __half* w_proj = w16 + 110592;
    const __half* w_qkvt = w16 + 147456;
    const __half* w_projt= w16 + 258048;

    cudaFuncSetAttribute(k_convq, cudaFuncAttributeMaxDynamicSharedMemorySize, CONVQ_SMEM);
    cudaFuncSetAttribute(k_convp, cudaFuncAttributeMaxDynamicSharedMemorySize, CONVP_SMEM);

    k_wprep<<<288, 1024>>>(qkv_w, proj_w, qkvt_w, projt_w);

    // ---- pass 1 (spatial, L=1024) ----
    k_gn1s<<<NBT * 32, 256>>>(x);
    k_gn1at<<<dim3(16, 32), 256>>>(x, norm_g, norm_b);
    k_convq<<<dim3(256, 3), 256, CONVQ_SMEM>>>(nrm16, w_qkv, qkv_b, qk16, v16T, 10);
    k_attn1h<<<dim3(16, 96), 128>>>(qk16, v16T, att16);
    k_convp<<<256, 256, CONVP_SMEM>>>(att16, w_proj, proj_b, x, y, 10, 2);

    // ---- pass 2 (temporal, L=16) ----
    k_transpose2c<<<dim3(16, 48, 2), 256>>>();
    k_gn2h<<<2048, 128>>>(yt, normt_g, normt_b, nrm16);
    k_convq<<<dim3(256, 3), 256, CONVQ_SMEM>>>(nrm16, w_qkvt, qkvt_b, qk16, v16T, 4);
    k_attn2h<<<6144, 256>>>(qk16, v16T, att16);
    k_convp<<<256, 256, CONVP_SMEM>>>(att16, w_projt, projt_b, yt, xs, 4, 1);
    k_transpose3c<<<dim3(16, 48, 2), 256>>>(out);
}

// round 17
// speedup vs baseline: 1.0787x; 1.0004x over previous
#include <cuda_runtime.h>
#include <cuda_fp16.h>
#include <math.h>

#define NBT 32
#define CCH 192
#define TOT (NBT*CCH*1024)
typedef unsigned int uint32;

// fp32 scratch
__device__ float g_xs [TOT];          // z (bhw,c,t) in pass2
__device__ float g_y  [TOT];
__device__ float g_yt [TOT];
__device__ float g_stat[NBT*32*2];
// fp16 scratch
__device__ __half g_nrm16[32768*192];
__device__ __half g_qk16 [32768*384];
__device__ __half g_v16T [32768*192];
__device__ __half g_att16[32768*192];
__device__ __half g_w16  [294912];

// ---- helpers ----------------------------------------------------------------
__device__ __forceinline__ void mmah(float4 &c, const uint32* a, uint32 b0, uint32 b1) {
    asm("mma.sync.aligned.m16n8k16.row.col.f32.f16.f16.f32 "
        "{%0,%1,%2,%3},{%4,%5,%6,%7},{%8,%9},{%0,%1,%2,%3};"
        : "+f"(c.x), "+f"(c.y), "+f"(c.z), "+f"(c.w)
        : "r"(a[0]), "r"(a[1]), "r"(a[2]), "r"(a[3]), "r"(b0), "r"(b1));
}
__device__ __forceinline__ uint32 sptr(const void* p) {
    return (uint32)__cvta_generic_to_shared(p);
}
__device__ __forceinline__ void ldsm4(uint32* r, uint32 addr) {
    asm volatile("ldmatrix.sync.aligned.m8n8.x4.shared.b16 {%0,%1,%2,%3}, [%4];"
        : "=r"(r[0]), "=r"(r[1]), "=r"(r[2]), "=r"(r[3]) : "r"(addr));
}
__device__ __forceinline__ void cp16(uint32 s, const void* g) {
    asm volatile("cp.async.ca.shared.global [%0], [%1], 16;" :: "r"(s), "l"(g));
}
__device__ __forceinline__ void cp_commit() { asm volatile("cp.async.commit_group;"); }
template<int N> __device__ __forceinline__ void cp_wait() {
    asm volatile("cp.async.wait_group %0;" :: "n"(N));
}

// ---------------------------------------------------------------------------
// Weight fp16 prep
// ---------------------------------------------------------------------------
__global__ void k_wprep(const float* __restrict__ qw, const float* __restrict__ pw,
                        const float* __restrict__ qtw, const float* __restrict__ ptw) {
    int i = blockIdx.x * 1024 + threadIdx.x;
    float v;
    if      (i < 110592) v = qw[i];
    else if (i < 147456) v = pw[i - 110592];
    else if (i < 258048) v = qtw[i - 147456];
    else                 v = ptw[i - 258048];
    g_w16[i] = __float2half(v);
}

// ---------------------------------------------------------------------------
// GroupNorm pass 1 stats
// ---------------------------------------------------------------------------
__global__ void k_gn1s(const float* __restrict__ x) {
    int n = blockIdx.x >> 5, g = blockIdx.x & 31;
    int b = n >> 4, t = n & 15;
    const float* xb = x + (((size_t)(b * CCH + g * 6) * 16 + t) << 10);
    int tid = threadIdx.x;
    float s = 0.f, q = 0.f;
    for (int i = tid; i < 6144; i += 256) {
        float v = xb[((size_t)(i >> 10) << 14) + (i & 1023)];
        s += v; q += v * v;
    }
    __shared__ float rs[256], rq[256];
    rs[tid] = s; rq[tid] = q;
    __syncthreads();
    for (int st = 128; st > 0; st >>= 1) {
        if (tid < st) { rs[tid] += rs[tid + st]; rq[tid] += rq[tid + st]; }
        __syncthreads();
    }
    if (tid == 0) {
        float mean = rs[0] / 6144.f;
        float var  = rq[0] / 6144.f - mean * mean;
        g_stat[blockIdx.x * 2]     = mean;
        g_stat[blockIdx.x * 2 + 1] = rsqrtf(var + 1e-5f);
    }
}

// ---------------------------------------------------------------------------
// GroupNorm pass 1 apply, tiled coalesced
// ---------------------------------------------------------------------------
__global__ __launch_bounds__(256) void k_gn1at(const float* __restrict__ x,
                                               const float* __restrict__ gam,
                                               const float* __restrict__ bet) {
    __shared__ __half sbuf[64 * 200];
    const int hw0 = blockIdx.x * 64, bt = blockIdx.y;
    const int b = bt >> 4, t = bt & 15;
    const int tid = threadIdx.x;
    #pragma unroll
    for (int rep = 0; rep < 3; rep++) {
        const int c = rep * 64 + (tid >> 2);
        const int hwq = (tid & 3) * 16;
        const int g = c / 6;
        const float mu = g_stat[(bt * 32 + g) * 2];
        const float iv = g_stat[(bt * 32 + g) * 2 + 1];
        const float ga = gam[c] * iv;
        const float be = bet[c] - mu * ga;
        const float* src = x + (((size_t)(b * CCH + c) * 16 + t) << 10) + hw0 + hwq;
        #pragma unroll
        for (int j = 0; j < 16; j += 4) {
            float4 v = *(const float4*)(src + j);
            sbuf[(hwq + j + 0) * 200 + c] = __float2half(v.x * ga + be);
            sbuf[(hwq + j + 1) * 200 + c] = __float2half(v.y * ga + be);
            sbuf[(hwq + j + 2) * 200 + c] = __float2half(v.z * ga + be);
            sbuf[(hwq + j + 3) * 200 + c] = __float2half(v.w * ga + be);
        }
    }
    __syncthreads();
    #pragma unroll
    for (int i = tid; i < 1536; i += 256) {
        int tok = i / 24, seg = i - tok * 24;
        *(uint4*)(g_nrm16 + ((size_t)(bt * 1024 + hw0 + tok)) * 192 + seg * 8) =
            *(const uint4*)(sbuf + tok * 200 + seg * 8);
    }
}

// ---------------------------------------------------------------------------
// GroupNorm pass 2
// ---------------------------------------------------------------------------
__global__ void k_gn2h(const float* __restrict__ X, const float* __restrict__ gam,
                       const float* __restrict__ bet, __half* __restrict__ out16) {
    int n = blockIdx.x;
    __shared__ float buf[3072];
    __shared__ float mu[32], iv[32];
    int tid = threadIdx.x;
    const float4* xb = (const float4*)(X + (size_t)n * 3072);
    for (int i = tid; i < 768; i += 128) ((float4*)buf)[i] = xb[i];
    __syncthreads();
    int w = tid >> 5, lane = tid & 31;
    for (int g = w; g < 32; g += 4) {
        float v0 = buf[g * 96 + lane], v1 = buf[g * 96 + 32 + lane], v2 = buf[g * 96 + 64 + lane];
        float s = v0 + v1 + v2, q = v0 * v0 + v1 * v1 + v2 * v2;
        #pragma unroll
        for (int off = 16; off; off >>= 1) {
            s += __shfl_xor_sync(0xffffffffu, s, off);
            q += __shfl_xor_sync(0xffffffffu, q, off);
        }
        if (lane == 0) {
            float m = s / 96.f, va = q / 96.f - m * m;
            mu[g] = m; iv[g] = rsqrtf(va + 1e-5f);
        }
    }
    __syncthreads();
    __half* ob = out16 + (size_t)n * 3072;
    for (int j = tid; j < 3072; j += 128) {
        int t = j / 192, c = j - t * 192;
        int g = c / 6;
        ob[j] = __float2half((buf[c * 16 + t] - mu[g]) * iv[g] * gam[c] + bet[c]);
    }
}

// ---------------------------------------------------------------------------
// c-blocked transposes
// ---------------------------------------------------------------------------
__global__ __launch_bounds__(256) void k_transpose2c() {  // y (bt,c,hw) -> yt (bhw,c,t)
    __shared__ float sb[5168];
    const int hw0 = blockIdx.x * 64, c0 = blockIdx.y * 4, b = blockIdx.z;
    const int tid = threadIdx.x, w = tid >> 5, lane = tid & 31;
    #pragma unroll
    for (int it = 0; it < 8; it++) {
        int p = it * 8 + w;
        int c = p >> 4, t = p & 15;
        float2 v = *(const float2*)&g_y[(((size_t)(b * 16 + t) * CCH + c0 + c) << 10)
                                        + hw0 + lane * 2];
        sb[c * 1296 + (lane * 2) * 20 + t]     = v.x;
        sb[c * 1296 + (lane * 2 + 1) * 20 + t] = v.y;
    }
    __syncthreads();
    #pragma unroll
    for (int i2 = 0; i2 < 4; i2++) {
        int u = tid + 256 * i2;
        int hw = u >> 4, q = u & 15;
        int c = q >> 2, t4 = (q & 3) * 4;
        *(float4*)&g_yt[((size_t)(b * 1024 + hw0 + hw) * CCH + c0 + c) * 16 + t4] =
            *(const float4*)&sb[c * 1296 + hw * 20 + t4];
    }
}

__global__ __launch_bounds__(256) void k_transpose3c(float* __restrict__ out) {
    __shared__ float sb[5168];
    const int hw0 = blockIdx.x * 64, c0 = blockIdx.y * 4, b = blockIdx.z;
    const int tid = threadIdx.x, w = tid >> 5, lane = tid & 31;
    #pragma unroll
    for (int i2 = 0; i2 < 4; i2++) {
        int u = tid + 256 * i2;
        int hw = u >> 4, q = u & 15;
        int c = q >> 2, t4 = (q & 3) * 4;
        *(float4*)&sb[c * 1296 + hw * 20 + t4] =
            *(const float4*)&g_xs[((size_t)(b * 1024 + hw0 + hw) * CCH + c0 + c) * 16 + t4];
    }
    __syncthreads();
    #pragma unroll
    for (int it = 0; it < 8; it++) {
        int p = it * 8 + w;
        int c = p >> 4, t = p & 15;
        float2 v = make_float2(sb[c * 1296 + (lane * 2) * 20 + t],
                               sb[c * 1296 + (lane * 2 + 1) * 20 + t]);
        *(float2*)&out[(((size_t)(b * CCH + c0 + c) * 16 + t) << 10) + hw0 + lane * 2] = v;
    }
}

// ---------------------------------------------------------------------------
// QKV conv: X-persistent + W-part-resident (barrier-free inner loop).
// ---------------------------------------------------------------------------
#define CONVQ_SMEM 100352

__global__ __launch_bounds__(256, 2) void k_convq(
    const __half* __restrict__ X, const __half* __restrict__ W,
    const float* __restrict__ bias,
    __half* __restrict__ outqk, __half* __restrict__ outv, int ls) {
    extern __shared__ __half SM[];
    const int tid = threadIdx.x, lane = tid & 31, w = tid >> 5;
    const int r = lane >> 2, tg = lane & 3;
    const int g0 = blockIdx.x * 128, ha = blockIdx.y;
    const int L = 1 << ls, Lm1 = L - 1;
    const int aRow = (lane & 7) + 8 * ((lane >> 3) & 1);
    const int aCol = 8 * (lane >> 4);
    const int bRow = (lane & 7) + 8 * (lane >> 4);
    const int bCol = 8 * ((lane >> 3) & 1);
    const int ob0 = (w >> 1) * 16, coff = (w & 1) * 64;
    const __half* wbase = W + (size_t)(ha * 192) * 192;
    __half* E = SM + 40960;

    {
        const int stok = tid >> 1, xh = (tid & 1) * 96;
        const __half* xsrc = X + (size_t)(g0 + stok) * 192 + xh;
        #pragma unroll
        for (int s = 0; s < 12; s++)
            cp16(sptr(&SM[stok * 200 + xh + s * 8]), xsrc + s * 8);
        cp_commit();
    }

    for (int i = 0; i < 3; i++) {
        #pragma unroll
        for (int s = 0; s < 6; s++) {
            int u = tid + 256 * s;
            int c = u >> 8, rem = u & 255;
            int o = rem >> 2, k8 = (rem & 3) * 8;
            cp16(sptr(&SM[25600 + c * 2560 + o * 40 + k8]),
                 wbase + (size_t)(i * 64 + o) * 192 + c * 32 + k8);
        }
        cp_commit();
        cp_wait<0>();
        __syncthreads();

        float4 acc[8];
        #pragma unroll
        for (int nt = 0; nt < 8; nt++) acc[nt] = make_float4(0.f, 0.f, 0.f, 0.f);

        #pragma unroll
        for (int c = 0; c < 6; c++) {
            const int wsb = 25600 + c * 2560;
            #pragma unroll
            for (int ks = 0; ks < 2; ks++) {
                uint32 a[4];
                ldsm4(a, sptr(&SM[wsb + (ob0 + aRow) * 40 + ks * 16 + aCol]));
                #pragma unroll
                for (int pr = 0; pr < 4; pr++) {
                    uint32 b[4];
                    ldsm4(b, sptr(&SM[(coff + pr * 16 + bRow) * 200 + c * 32 + ks * 16 + bCol]));
                    mmah(acc[2 * pr],     a, b[0], b[1]);
                    mmah(acc[2 * pr + 1], a, b[2], b[3]);
                }
            }
        }

        const int o0 = ha * 192 + i * 64;
        const int c0 = ob0 + r;
        const float ba = bias[o0 + c0], bb = bias[o0 + c0 + 8];
        if (i < 2) {
            #pragma unroll
            for (int nt = 0; nt < 8; nt++) {
                const int tok = coff + nt * 8 + 2 * tg;
                E[tok * 72 + c0]           = __float2half(acc[nt].x + ba);
                E[(tok + 1) * 72 + c0]     = __float2half(acc[nt].y + ba);
                E[tok * 72 + c0 + 8]       = __float2half(acc[nt].z + bb);
                E[(tok + 1) * 72 + c0 + 8] = __float2half(acc[nt].w + bb);
            }
            __syncthreads();
            const int base = ha * 128 + i * 64;
            #pragma unroll
            for (int ii = 0; ii < 4; ii++) {
                int j = tid + 256 * ii;
                int tok = j >> 3, seg = j & 7;
                *(uint4*)(outqk + (size_t)(g0 + tok) * 384 + base + seg * 8) =
                    *(const uint4*)(E + tok * 72 + seg * 8);
            }
        } else {
            #pragma unroll
            for (int nt = 0; nt < 8; nt++) {
                const int tok = coff + nt * 8 + 2 * tg;
                *(__half2*)(E + c0 * 136 + tok) =
                    __floats2half2_rn(acc[nt].x + ba, acc[nt].y + ba);
                *(__half2*)(E + (c0 + 8) * 136 + tok) =
                    __floats2half2_rn(acc[nt].z + bb, acc[nt].w + bb);
            }
            __syncthreads();
            const int cvb = ha * 64;
            #pragma unroll
            for (int ii = 0; ii < 4; ii++) {
                int j = tid + 256 * ii;
                int ch = j >> 4, seg = j & 15;
                int gt = g0 + seg * 8;
                int img = gt >> ls, tok = gt & Lm1;
                *(uint4*)(outv + ((size_t)img * 192 + cvb + ch) * L + tok) =
                    *(const uint4*)(E + ch * 136 + seg * 8);
            }
        }
        __syncthreads();
    }
}

// ---------------------------------------------------------------------------
// Proj conv: X-persistent + W-part-resident, fp32 out + residual.
// ---------------------------------------------------------------------------
#define CONVP_SMEM 81920

__global__ __launch_bounds__(256, 2) void k_convp(
    const __half* __restrict__ X, const __half* __restrict__ W,
    const float* __restrict__ bias, const float* __restrict__ res,
    float* __restrict__ outf, int ls, int mode) {
    extern __shared__ __half SM[];
    const int tid = threadIdx.x, lane = tid & 31, w = tid >> 5;
    const int r = lane >> 2, tg = lane & 3;
    const int g0 = blockIdx.x * 128;
    const int L = 1 << ls, Lm1 = L - 1;
    const int aRow = (lane & 7) + 8 * ((lane >> 3) & 1);
    const int aCol = 8 * (lane >> 4);
    const int bRow = (lane & 7) + 8 * (lane >> 4);
    const int bCol = 8 * ((lane >> 3) & 1);
    const int ob0 = (w >> 1) * 16, coff = (w & 1) * 64;

    {
        const int stok = tid >> 1, xh = (tid & 1) * 96;
        const __half* xsrc = X + (size_t)(g0 + stok) * 192 + xh;
        #pragma unroll
        for (int s = 0; s < 12; s++)
            cp16(sptr(&SM[stok * 200 + xh + s * 8]), xsrc + s * 8);
        cp_commit();
    }

    for (int i = 0; i < 3; i++) {
        #pragma unroll
        for (int s = 0; s < 6; s++) {
            int u = tid + 256 * s;
            int c = u >> 8, rem = u & 255;
            int o = rem >> 2, k8 = (rem & 3) * 8;
            cp16(sptr(&SM[25600 + c * 2560 + o * 40 + k8]),
                 W + (size_t)(i * 64 + o) * 192 + c * 32 + k8);
        }
        cp_commit();
        cp_wait<0>();
        __syncthreads();

        float4 acc[8];
        #pragma unroll
        for (int nt = 0; nt < 8; nt++) acc[nt] = make_float4(0.f, 0.f, 0.f, 0.f);

        #pragma unroll
        for (int c = 0; c < 6; c++) {
            const int wsb = 25600 + c * 2560;
            #pragma unroll
            for (int ks = 0; ks < 2; ks++) {
                uint32 a[4];
                ldsm4(a, sptr(&SM[wsb + (ob0 + aRow) * 40 + ks * 16 + aCol]));
                #pragma unroll
                for (int pr = 0; pr < 4; pr++) {
                    uint32 b[4];
                    ldsm4(b, sptr(&SM[(coff + pr * 16 + bRow) * 200 + c * 32 + ks * 16 + bCol]));
                    mmah(acc[2 * pr],     a, b[0], b[1]);
                    mmah(acc[2 * pr + 1], a, b[2], b[3]);
                }
            }
        }

        const int oa = i * 64 + ob0 + r;
        const int obr = oa + 8;
        const float ba = bias[oa], bb = bias[obr];
        #pragma unroll
        for (int nt = 0; nt < 8; nt++) {
            int g = g0 + coff + nt * 8 + 2 * tg;
            float vax = acc[nt].x + ba, vay = acc[nt].y + ba;
            float vbx = acc[nt].z + bb, vby = acc[nt].w + bb;
            int n = g >> ls, l = g & Lm1;
            size_t pAa = ((size_t)n * 192 + oa) * L + l;
            size_t pBb = ((size_t)n * 192 + obr) * L + l;
            float2 va = make_float2(vax, vay);
            float2 vb = make_float2(vbx, vby);
            if (mode == 1) {
                float2 qa = *(const float2*)(res + pAa);
                float2 qb = *(const float2*)(res + pBb);
                va.x += qa.x; va.y += qa.y; vb.x += qb.x; vb.y += qb.y;
            } else {
                int b = n >> 4, t = n & 15;
                size_t xa = (((size_t)(b * 192 + oa) * 16 + t) << 10) + l;
                size_t xb = (((size_t)(b * 192 + obr) * 16 + t) << 10) + l;
                float2 qa = *(const float2*)(res + xa);
                float2 qb = *(const float2*)(res + xb);
                va.x += qa.x; va.y += qa.y; vb.x += qb.x; vb.y += qb.y;
            }
            *(float2*)(outf + pAa) = va;
            *(float2*)(outf + pBb) = vb;
        }
        __syncthreads();
    }
}

// ---------------------------------------------------------------------------
// Attention pass 1: flash fp16 MMA, K AND V double-buffered, 2 syncs/kt.
// smem: U + K0 + K1 + V0 + V1 = 5 x [64][72] half = 46,080 B (4 CTAs/SM).
// ---------------------------------------------------------------------------
#define HS 72

__global__ __launch_bounds__(128, 4) void k_attn1h(const __half* __restrict__ qk,
                                                   const __half* __restrict__ vT,
                                                   __half* __restrict__ outh) {
    __shared__ __align__(16) __half smh[5 * 64 * HS];
    __half* U  = smh;
    __half* KB0 = smh + 64 * HS;
    __half* KB1 = smh + 2 * 64 * HS;
    __half* VB0 = smh + 3 * 64 * HS;
    __half* VB1 = smh + 4 * 64 * HS;

    const int tid = threadIdx.x, lane = tid & 31, w = tid >> 5;
    const int r = lane >> 2, tg = lane & 3;
    const int bh = blockIdx.y, n = bh / 3, h = bh % 3;
    const int q0 = blockIdx.x * 64;
    const __half* Qg = qk + ((size_t)(n * 1024) + q0) * 384 + h * 128;
    const __half* Kg = qk + (size_t)(n * 1024) * 384 + h * 128 + 64;
    const __half* Vg = vT + (size_t)(n * 192 + h * 64) * 1024;
    const int aRow = (lane & 7) + 8 * ((lane >> 3) & 1);
    const int aCol = 8 * (lane >> 4);
    const int bRow = (lane & 7) + 8 * (lane >> 4);
    const int bCol = 8 * ((lane >> 3) & 1);

    const int stok = tid >> 1, seg = (tid & 1) * 32;

    // prologue: stage K0/V0 tile 0 and Q (one group)
    #pragma unroll
    for (int i = 0; i < 4; i++) {
        cp16(sptr(&KB0[stok * HS + seg + i * 8]), Kg + (size_t)stok * 384 + seg + i * 8);
        cp16(sptr(&VB0[stok * HS + seg + i * 8]), Vg + (size_t)stok * 1024 + seg + i * 8);
        cp16(sptr(&U[stok * HS + seg + i * 8]),   Qg + (size_t)stok * 384 + seg + i * 8);
    }
    cp_commit();
    cp_wait<0>();
    __syncthreads();

    uint32 qa[4][4];
    #pragma unroll
    for (int ks = 0; ks < 4; ks++)
        ldsm4(qa[ks], sptr(&U[(16 * w + aRow) * HS + ks * 16 + aCol]));

    float4 o[8];
    #pragma unroll
    for (int nt = 0; nt < 8; nt++) o[nt] = make_float4(0.f, 0.f, 0.f, 0.f);
    float m0 = -1e30f, m1 = -1e30f, s0 = 0.f, s1 = 0.f;
    __half* pr0h = U + (16 * w + r) * HS;
    __half* pr1h = U + (16 * w + r + 8) * HS;
    const float SC = 0.125f;

    for (int kt = 0; kt < 16; kt++) {
        const int buf = kt & 1;
        // prefetch K/V(kt+1) into buf^1 (last read at kt-1, protected by end sync)
        if (kt < 15) {
            const int sb = (kt + 1) * 64;
            __half* Kn = buf ? KB0 : KB1;
            __half* Vn = buf ? VB0 : VB1;
            #pragma unroll
            for (int i = 0; i < 4; i++) {
                cp16(sptr(&Kn[stok * HS + seg + i * 8]),
                     Kg + (size_t)(sb + stok) * 384 + seg + i * 8);
                cp16(sptr(&Vn[stok * HS + seg + i * 8]),
                     Vg + (size_t)stok * 1024 + sb + seg + i * 8);
            }
            cp_commit();
            cp_wait<1>();
        } else {
            cp_wait<0>();
        }
        __syncthreads();   // visibility of kt tiles
        const __half* Ks = buf ? KB1 : KB0;
        const __half* Vs = buf ? VB1 : VB0;

        // S = Q K^T
        float4 sc[8];
        #pragma unroll
        for (int nt = 0; nt < 8; nt++) sc[nt] = make_float4(0.f, 0.f, 0.f, 0.f);
        #pragma unroll
        for (int ks = 0; ks < 4; ks++) {
            #pragma unroll
            for (int pr = 0; pr < 4; pr++) {
                uint32 b[4];
                ldsm4(b, sptr(&Ks[(pr * 16 + bRow) * HS + ks * 16 + bCol]));
                mmah(sc[2 * pr],     qa[ks], b[0], b[1]);
                mmah(sc[2 * pr + 1], qa[ks], b[2], b[3]);
            }
        }

        // online softmax
        float tm0 = -1e30f, tm1 = -1e30f;
        #pragma unroll
        for (int nt = 0; nt < 8; nt++) {
            tm0 = fmaxf(tm0, fmaxf(sc[nt].x, sc[nt].y));
            tm1 = fmaxf(tm1, fmaxf(sc[nt].z, sc[nt].w));
        }
        tm0 = fmaxf(tm0, __shfl_xor_sync(0xffffffffu, tm0, 1));
        tm0 = fmaxf(tm0, __shfl_xor_sync(0xffffffffu, tm0, 2));
        tm1 = fmaxf(tm1, __shfl_xor_sync(0xffffffffu, tm1, 1));
        tm1 = fmaxf(tm1, __shfl_xor_sync(0xffffffffu, tm1, 2));
        tm0 *= SC; tm1 *= SC;
        float nm0 = fmaxf(m0, tm0), nm1 = fmaxf(m1, tm1);
        float a0 = __expf(m0 - nm0), a1 = __expf(m1 - nm1);
        float t0 = 0.f, t1 = 0.f;
        #pragma unroll
        for (int nt = 0; nt < 8; nt++) {
            float px = __expf(fmaf(sc[nt].x, SC, -nm0));
            float py = __expf(fmaf(sc[nt].y, SC, -nm0));
            float pz = __expf(fmaf(sc[nt].z, SC, -nm1));
            float pw = __expf(fmaf(sc[nt].w, SC, -nm1));
            t0 += px + py; t1 += pz + pw;
            const int col = nt * 8 + 2 * tg;
            *(__half2*)(pr0h + col) = __floats2half2_rn(px, py);
            *(__half2*)(pr1h + col) = __floats2half2_rn(pz, pw);
            o[nt].x *= a0; o[nt].y *= a0;
            o[nt].z *= a1; o[nt].w *= a1;
        }
        t0 += __shfl_xor_sync(0xffffffffu, t0, 1);
        t0 += __shfl_xor_sync(0xffffffffu, t0, 2);
        t1 += __shfl_xor_sync(0xffffffffu, t1, 1);
        t1 += __shfl_xor_sync(0xffffffffu, t1, 2);
        s0 = s0 * a0 + t0;
        s1 = s1 * a1 + t1;
        m0 = nm0; m1 = nm1;
        __syncwarp();

        // O += P V (V already resident)
        #pragma unroll
        for (int ks = 0; ks < 4; ks++) {
            uint32 a[4];
            ldsm4(a, sptr(&U[(16 * w + aRow) * HS + ks * 16 + aCol]));
            #pragma unroll
            for (int pr = 0; pr < 4; pr++) {
                uint32 b[4];
                ldsm4(b, sptr(&Vs[(pr * 16 + bRow) * HS + ks * 16 + bCol]));
                mmah(o[2 * pr],     a, b[0], b[1]);
                mmah(o[2 * pr + 1], a, b[2], b[3]);
            }
        }
        __syncthreads();   // buffer-reuse protection for next prefetch
    }

    float i0 = 1.f / s0, i1 = 1.f / s1;
    __half* Os = KB0;
    #pragma unroll
    for (int nt = 0; nt < 8; nt++) {
        const int col = nt * 8 + 2 * tg;
        *(__half2*)(Os + (16 * w + r) * HS + col)     = __floats2half2_rn(o[nt].x * i0, o[nt].y * i0);
        *(__half2*)(Os + (16 * w + r + 8) * HS + col) = __floats2half2_rn(o[nt].z * i1, o[nt].w * i1);
    }
    __syncthreads();
    __half* dst = outh + ((size_t)(n * 1024) + q0 + stok) * 192 + h * 64 + seg;
    #pragma unroll
    for (int i = 0; i < 4; i++)
        *(uint4*)(dst + i * 8) = *(const uint4*)(Os + stok * HS + seg + i * 8);
}

// ---------------------------------------------------------------------------
// Attention pass 2: L=16, scalar fp32 from half inputs
// ---------------------------------------------------------------------------
__global__ void k_attn2h(const __half* __restrict__ qkh, const __half* __restrict__ vTh,
                         __half* __restrict__ outh) {
    __shared__ float qs[16][68], ks[16][68], vs[1024], S[16 * 17];
    int bh = blockIdx.x, n = bh / 3, h = bh % 3;
    int tid = threadIdx.x;
    const __half* Qb = qkh + (size_t)(n * 16) * 384 + h * 128;
    const __half* Vb = vTh + (size_t)(n * 192 + h * 64) * 16;
    for (int i = tid; i < 1024; i += 256) {
        int q = i >> 6, c = i & 63;
        qs[q][c] = __half2float(Qb[(size_t)q * 384 + c]) * 0.125f;
        ks[q][c] = __half2float(Qb[(size_t)q * 384 + 64 + c]);
        vs[i] = __half2float(Vb[i]);
    }
    __syncthreads();
    {
        int q = tid >> 4, s = tid & 15;
        float a = 0.f;
        #pragma unroll
        for (int c = 0; c < 64; c++) a += qs[q][c] * ks[s][c];
        S[q * 17 + s] = a;
    }
    __syncthreads();
    if (tid < 16) {
        float* row = S + tid * 17;
        float m = -1e30f;
        #pragma unroll
        for (int s = 0; s < 16; s++) m = fmaxf(m, row[s]);
        float sum = 0.f;
        #pragma unroll
        for (int s = 0; s < 16; s++) { float e = __expf(row[s] - m); row[s] = e; sum += e; }
        float inv = 1.f / sum;
        #pragma unroll
        for (int s = 0; s < 16; s++) row[s] *= inv;
    }
    __syncthreads();
    {
        int q = tid & 15;
        int cb = (tid >> 4) << 2;
        float a0 = 0.f, a1 = 0.f, a2 = 0.f, a3 = 0.f;
        #pragma unroll
        for (int s = 0; s < 16; s++) {
            float sv = S[q * 17 + s];
            a0 += vs[(cb + 0) * 16 + s] * sv;
            a1 += vs[(cb + 1) * 16 + s] * sv;
            a2 += vs[(cb + 2) * 16 + s] * sv;
            a3 += vs[(cb + 3) * 16 + s] * sv;
        }
        __half* ob = outh + ((size_t)(n * 16) + q) * 192 + h * 64 + cb;
        ob[0] = __float2half(a0);
        ob[1] = __float2half(a1);
        ob[2] = __float2half(a2);
        ob[3] = __float2half(a3);
    }
}

// ---------------------------------------------------------------------------
extern "C" void kernel_launch(void* const* d_in, const int* in_sizes, int n_in,
                              void* d_out, int out_size) {
    const float* x       = (const float*)d_in[0];
    const float* norm_g  = (const float*)d_in[1];
    const float* norm_b  = (const float*)d_in[2];
    const float* qkv_w   = (const float*)d_in[3];
    const float* qkv_b   = (const float*)d_in[4];
    const float* proj_w  = (const float*)d_in[5];
    const float* proj_b  = (const float*)d_in[6];
    const float* normt_g = (const float*)d_in[7];
    const float* normt_b = (const float*)d_in[8];
    const float* qkvt_w  = (const float*)d_in[9];
    const float* qkvt_b  = (const float*)d_in[10];
    const float* projt_w = (const float*)d_in[11];
    const float* projt_b = (const float*)d_in[12];
    float* out = (float*)d_out;

    float *xs, *y, *yt;
    __half *nrm16, *qk16, *v16T, *att16, *w16;
    cudaGetSymbolAddress((void**)&xs,    g_xs);
    cudaGetSymbolAddress((void**)&y,     g_y);
    cudaGetSymbolAddress((void**)&yt,    g_yt);
    cudaGetSymbolAddress((void**)&nrm16, g_nrm16);
    cudaGetSymbolAddress((void**)&qk16,  g_qk16);
    cudaGetSymbolAddress((void**)&v16T,  g_v16T);
    cudaGetSymbolAddress((void**)&att16, g_att16);
    cudaGetSymbolAddress((void**)&w16,   g_w16);

    const __half* w_qkv  = w16;
    const __half* w_proj = w16 + 110592;
    const __half* w_qkvt = w16 + 147456;
    const __half* w_projt= w16 + 258048;

    cudaFuncSetAttribute(k_convq, cudaFuncAttributeMaxDynamicSharedMemorySize, CONVQ_SMEM);
    cudaFuncSetAttribute(k_convp, cudaFuncAttributeMaxDynamicSharedMemorySize, CONVP_SMEM);

    k_wprep<<<288, 1024>>>(qkv_w, proj_w, qkvt_w, projt_w);

    // ---- pass 1 (spatial, L=1024) ----
    k_gn1s<<<NBT * 32, 256>>>(x);
    k_gn1at<<<dim3(16, 32), 256>>>(x, norm_g, norm_b);
    k_convq<<<dim3(256, 3), 256, CONVQ_SMEM>>>(nrm16, w_qkv, qkv_b, qk16, v16T, 10);
    k_attn1h<<<dim3(16, 96), 128>>>(qk16, v16T, att16);
    k_convp<<<256, 256, CONVP_SMEM>>>(att16, w_proj, proj_b, x, y, 10, 2);

    // ---- pass 2 (temporal, L=16) ----
    k_transpose2c<<<dim3(16, 48, 2), 256>>>();
    k_gn2h<<<2048, 128>>>(yt, normt_g, normt_b, nrm16);
    k_convq<<<dim3(256, 3), 256, CONVQ_SMEM>>>(nrm16, w_qkvt, qkvt_b, qk16, v16T, 4);
    k_attn2h<<<6144, 256>>>(qk16, v16T, att16);
    k_convp<<<256, 256, CONVP_SMEM>>>(att16, w_projt, projt_b, yt, xs, 4, 1);
    k_transpose3c<<<dim3(16, 48, 2), 256>>>(out);
}